// round 13
// baseline (speedup 1.0000x reference)
#include <cuda_runtime.h>
#include <cuda_fp16.h>
#include <cstdint>
#include <math.h>

#define NB   8
#define LDQ  2048
#define LMEM 512
#define DIN  1024
#define HID  1024

// ---------------- scratch (__device__ globals; no allocations allowed) ----
__device__ __half g_input_dot[(size_t)NB * LDQ * HID];   // 32 MB
__device__ __half g_memory_dot[(size_t)NB * LMEM * HID]; // 8 MB
__device__ float  g_att[(size_t)NB * LDQ * LMEM];        // 32 MB (f32 logits)
__device__ __half g_attp[(size_t)NB * LDQ * LMEM];       // 16 MB (fp16 probs)
__device__ __half g_out_one[(size_t)NB * LDQ * DIN];     // 32 MB
__device__ __half g_w1t[(size_t)DIN * HID];              // 2 MB
__device__ __half g_wmt[(size_t)DIN * HID];              // 2 MB
__device__ __half g_w2t[(size_t)2 * DIN * HID];          // 4 MB
__device__ __half g_memt[(size_t)NB * DIN * LMEM];       // 8 MB
__device__ __half g_xh[(size_t)NB * LDQ * DIN];          // 32 MB (x as fp16)
__device__ __half g_memh[(size_t)NB * LMEM * DIN];       // 8 MB (mem as fp16)

enum { ACT_NONE = 0, ACT_RELU = 1, ACT_GATE = 2 };

// ---------------- helpers --------------------------------------------------
__device__ __forceinline__ uint32_t smem_u32(const void* p) {
    uint32_t a;
    asm("{ .reg .u64 t; cvta.to.shared.u64 t, %1; cvt.u32.u64 %0, t; }" : "=r"(a) : "l"(p));
    return a;
}
// bit-cast __half2 -> u32 (this toolchain lacks __half2_as_uint)
__device__ __forceinline__ uint32_t h2u(__half2 h) {
    __half2_raw r = *reinterpret_cast<__half2_raw*>(&h);
    return (uint32_t)r.x | ((uint32_t)r.y << 16);
}

#define CP16(dst, src) \
    asm volatile("cp.async.cg.shared.global [%0], [%1], 16;" :: "r"(dst), "l"(src))
#define CP_COMMIT() asm volatile("cp.async.commit_group;")
#define CP_WAIT1()  asm volatile("cp.async.wait_group 1;")

#define LDSM4(r0, r1, r2, r3, addr) \
    asm volatile("ldmatrix.sync.aligned.m8n8.x4.shared.b16 {%0,%1,%2,%3}, [%4];" \
        : "=r"(r0), "=r"(r1), "=r"(r2), "=r"(r3) : "r"(addr))

// fp16 tensor-core mma, fp32 accumulate
__device__ __forceinline__ void mma_f16(float* d, const uint32_t* a, const uint32_t* b) {
    asm volatile(
        "mma.sync.aligned.m16n8k16.row.col.f32.f16.f16.f32 "
        "{%0,%1,%2,%3}, {%4,%5,%6,%7}, {%8,%9}, {%0,%1,%2,%3};"
        : "+f"(d[0]), "+f"(d[1]), "+f"(d[2]), "+f"(d[3])
        : "r"(a[0]), "r"(a[1]), "r"(a[2]), "r"(a[3]), "r"(b[0]), "r"(b[1]));
}

// ---------------- fp16 mma.sync NT GEMM: C[M,N] = A[M,K] * B[N,K]^T -------
// BM=128, BN=128, BK=64 halves. 128 threads, 4 warps (2x2), warp tile 64x64.
// 2 CTAs/SM. 3-stage cp.async pipeline, one barrier per mainloop iteration.
// Fragment DOUBLE-BUFFER across k16 steps: in step ks we issue the 8 LDSM for
// ks+1, then the 32 MMAs of ks (each LDSM covered by >=32 MMA issues). The
// once-per-iter frag[0] load after the barrier is covered by sliding the
// 16-op cp.async prefetch block between it and its first consumer.
// Smem rows: 64 halves data + 8 pad = 36 words (144 B); conflict-free.
static constexpr int AROW_W = 36;                  // words per A/B smem row
static constexpr int ASZ = 128 * AROW_W;           // words per A stage
static constexpr int BSZ = 128 * AROW_W;           // words per B stage
static constexpr int STAGES = 3;
static constexpr int GEMM_SMEM = (ASZ + BSZ) * STAGES * 4;   // 110592 B

// Separate K indices: ka for the (possibly switched) A source, kb for B.
__device__ __forceinline__ void load_tile(
    uint32_t sb, int s, const __half* __restrict__ Ap, const __half* __restrict__ Bp,
    int m0, int n0, int ka, int kb, int lda, int ldb, int t)
{
    const uint32_t as = sb + s * (ASZ * 4);
    const uint32_t bs = sb + STAGES * (ASZ * 4) + s * (BSZ * 4);
    const int r  = t >> 3;            // 0..15
    const int c4 = (t & 7) * 4;       // word offset in row (16B chunks, 8/row)
    const __half* ag = &Ap[(size_t)(m0 + r) * lda + ka + (t & 7) * 8];
#pragma unroll
    for (int q = 0; q < 8; q++)
        CP16(as + ((r + q * 16) * AROW_W + c4) * 4, ag + (size_t)(q * 16) * lda);
    const __half* bg = &Bp[(size_t)(n0 + r) * ldb + kb + (t & 7) * 8];
#pragma unroll
    for (int q = 0; q < 8; q++)
        CP16(bs + ((r + q * 16) * AROW_W + c4) * 4, bg + (size_t)(q * 16) * ldb);
    CP_COMMIT();
}

template <int ACT, bool DUALA, bool OUTF32>
__global__ void __launch_bounds__(128, 2)
mma_gemm(const __half* __restrict__ A1, const __half* __restrict__ A2,
         const __half* __restrict__ B, const float* __restrict__ bias,
         void* __restrict__ Cv,
         int K, int Ksplit, int lda, int ldb, int ldc,
         long long sA, long long sB, long long sC, float scale)
{
    extern __shared__ float sm[];
    const uint32_t sb = smem_u32(sm);

    const int t    = threadIdx.x;
    const int wid  = t >> 5;
    const int lane = t & 31;
    const int gid  = lane >> 2;      // 0..7
    const int tig  = lane & 3;       // 0..3
    const int z = blockIdx.z;
    A1 += (size_t)z * sA;
    A2 += (size_t)z * sA;
    B  += (size_t)z * sB;
    const int m0 = blockIdx.y * 128;
    const int n0 = blockIdx.x * 128;

    const int NI = K >> 6;           // BK = 64 halves

    const int mb = (wid >> 1) * 64;   // warp row offset in tile (2x2 warp grid)
    const int nb = (wid & 1) * 64;    // warp col offset in tile

    // ldmatrix per-lane base addresses (bytes); stage/mi/ks offsets added later.
    const uint32_t a_lm = sb
        + (((mb + (lane & 15)) * AROW_W + (lane >> 4) * 4) << 2);
    const uint32_t b_lm = sb + STAGES * (ASZ * 4)
        + (((nb + (lane & 7) + ((lane >> 4) << 3)) * AROW_W + ((lane >> 3) & 1) * 4) << 2);

    // prologue: prefetch STAGES-1 = 2 stages
#pragma unroll
    for (int s = 0; s < 2; s++) {
        const int k0 = s * 64;
        const __half* Ap = A1;
        int ka = k0;
        if (DUALA && k0 >= Ksplit) { Ap = A2; ka = k0 - Ksplit; }
        load_tile(sb, s, Ap, B, m0, n0, ka, k0, lda, ldb, t);
    }

    float acc[4][8][4];
#pragma unroll
    for (int i = 0; i < 4; i++)
#pragma unroll
        for (int j = 0; j < 8; j++)
#pragma unroll
            for (int q = 0; q < 4; q++) acc[i][j][q] = 0.0f;

    uint32_t af[2][4][4];
    uint32_t bf[2][8][2];

    for (int i = 0; i < NI; i++) {
        CP_WAIT1();
        __syncthreads();   // compute of iter i-1 done on all warps ->
                           // writing stage (i+2)%3 == (i-1)%3 below is WAR-safe.

        const int s = i % 3;
        const uint32_t a_s = a_lm + s * (ASZ * 4);
        const uint32_t b_s = b_lm + s * (BSZ * 4);

        // frag[0] for ks=0 (head exposure, covered by the cp.async block below)
#pragma unroll
        for (int mi = 0; mi < 4; mi++)
            LDSM4(af[0][mi][0], af[0][mi][1], af[0][mi][2], af[0][mi][3],
                  a_s + mi * (16 * AROW_W * 4));
#pragma unroll
        for (int g = 0; g < 4; g++)
            LDSM4(bf[0][2 * g][0], bf[0][2 * g][1],
                  bf[0][2 * g + 1][0], bf[0][2 * g + 1][1],
                  b_s + g * (16 * AROW_W * 4));

        // global prefetch for stage i+2 — 16 cp.async issues fill the gap
        // between the frag[0] LDSMs above and their first MMA consumer.
        const int nx = i + 2;
        if (nx < NI) {
            const int k0 = nx * 64;
            const __half* Ap = A1;
            int ka = k0;
            if (DUALA && k0 >= Ksplit) { Ap = A2; ka = k0 - Ksplit; }
            load_tile(sb, nx % 3, Ap, B, m0, n0, ka, k0, lda, ldb, t);
        } else {
            CP_COMMIT();   // keep group count in lockstep for CP_WAIT1
        }

#pragma unroll
        for (int ks = 0; ks < 4; ks++) {          // four k16 steps (+32 B each)
            const int cur = ks & 1;
            const int nxt = cur ^ 1;
            if (ks < 3) {
                // fragments for ks+1: each LDSM covered by the 32 MMAs below
#pragma unroll
                for (int mi = 0; mi < 4; mi++)
                    LDSM4(af[nxt][mi][0], af[nxt][mi][1],
                          af[nxt][mi][2], af[nxt][mi][3],
                          a_s + mi * (16 * AROW_W * 4) + (ks + 1) * 32);
#pragma unroll
                for (int g = 0; g < 4; g++)
                    LDSM4(bf[nxt][2 * g][0], bf[nxt][2 * g][1],
                          bf[nxt][2 * g + 1][0], bf[nxt][2 * g + 1][1],
                          b_s + g * (16 * AROW_W * 4) + (ks + 1) * 32);
            }
#pragma unroll
            for (int mi = 0; mi < 4; mi++)
#pragma unroll
                for (int nj = 0; nj < 8; nj++)
                    mma_f16(acc[mi][nj], af[cur][mi], bf[cur][nj]);
        }
    }

    // ---- epilogue ----
    float*  Cf = (float*)Cv  + (size_t)z * sC;
    __half* Ch = (__half*)Cv + (size_t)z * sC;
#pragma unroll
    for (int mi = 0; mi < 4; mi++) {
        const int r0 = m0 + mb + mi * 16 + gid;
#pragma unroll
        for (int nj = 0; nj < 8; nj++) {
            const int c0 = n0 + nb + nj * 8 + tig * 2;
            float v[4];
#pragma unroll
            for (int q = 0; q < 4; q++) v[q] = acc[mi][nj][q] * scale;
            if (ACT != ACT_NONE) {
                const float bb0 = __ldg(&bias[c0]);
                const float bb1 = __ldg(&bias[c0 + 1]);
                v[0] += bb0; v[1] += bb1; v[2] += bb0; v[3] += bb1;
            }
#pragma unroll
            for (int q = 0; q < 4; q++) {
                if (ACT == ACT_RELU) v[q] = fmaxf(v[q], 0.0f);
                if (ACT == ACT_GATE) {
                    const float sg = 1.0f / (1.0f + expf(-v[q]));
                    v[q] = sg * tanhf(v[q]);
                }
            }
            if (OUTF32) {
                *(float2*)&Cf[(size_t)r0 * ldc + c0]       = make_float2(v[0], v[1]);
                *(float2*)&Cf[(size_t)(r0 + 8) * ldc + c0] = make_float2(v[2], v[3]);
            } else {
                *(__half2*)&Ch[(size_t)r0 * ldc + c0] =
                    __floats2half2_rn(v[0], v[1]);
                *(__half2*)&Ch[(size_t)(r0 + 8) * ldc + c0] =
                    __floats2half2_rn(v[2], v[3]);
            }
        }
    }
}

// ---------------- fused prep: transposes + fp16 converts + mem passthrough -
__device__ __forceinline__ void do_transpose_h(
    const float* __restrict__ src, __half* __restrict__ dst,
    int R, int C, int tX, int tY, int t)
{
    __shared__ float tile[32][33];
    const int lx = t & 31, ly = t >> 5;   // 32 x 8
    const int x = tX * 32 + lx;
    const int y0 = tY * 32;
#pragma unroll
    for (int i = ly; i < 32; i += 8)
        tile[i][lx] = src[(size_t)(y0 + i) * C + x];
    __syncthreads();
    const int xo = tY * 32 + lx;
    const int yo0 = tX * 32;
#pragma unroll
    for (int i = ly; i < 32; i += 8)
        dst[(size_t)(yo0 + i) * R + xo] = __float2half_rn(tile[lx][i]);
}

static constexpr int PB_RX   = 16384;   // x -> half     (16M floats)
static constexpr int PB_RM   = 4096;    // mem -> half   (4M floats)
static constexpr int PB_CP   = 4096;    // mem -> out tail (f32 copy, 1M float4)
static constexpr int PB_W1   = 1024;    // W1t
static constexpr int PB_WM   = 1024;    // Wmt
static constexpr int PB_W2   = 2048;    // W2t
static constexpr int PB_MT   = 4096;    // memt (z=8)
static constexpr int PREP_BLOCKS =
    PB_RX + PB_RM + PB_CP + PB_W1 + PB_WM + PB_W2 + PB_MT;

__global__ void __launch_bounds__(256)
prep_k(const float* __restrict__ x, const float* __restrict__ mem,
       const float* __restrict__ W1, const float* __restrict__ Wm,
       const float* __restrict__ W2,
       __half* __restrict__ xh, __half* __restrict__ memh,
       __half* __restrict__ w1t, __half* __restrict__ wmt,
       __half* __restrict__ w2t, __half* __restrict__ memt,
       float* __restrict__ out_tail)
{
    int b = blockIdx.x;
    const int t = threadIdx.x;
    if (b < PB_RX) {
        const int i = b * 256 + t;
        float4 v = ((const float4*)x)[i];
        ((uint2*)xh)[i] = make_uint2(
            h2u(__floats2half2_rn(v.x, v.y)),
            h2u(__floats2half2_rn(v.z, v.w)));
        return;
    }
    b -= PB_RX;
    if (b < PB_RM) {
        const int i = b * 256 + t;
        float4 v = ((const float4*)mem)[i];
        ((uint2*)memh)[i] = make_uint2(
            h2u(__floats2half2_rn(v.x, v.y)),
            h2u(__floats2half2_rn(v.z, v.w)));
        return;
    }
    b -= PB_RM;
    if (b < PB_CP) {                 // exact mem passthrough to output tuple[1]
        const int i = b * 256 + t;
        ((float4*)out_tail)[i] = ((const float4*)mem)[i];
        return;
    }
    b -= PB_CP;
    if (b < PB_W1) { do_transpose_h(W1, w1t, DIN, HID, b & 31, b >> 5, t); return; }
    b -= PB_W1;
    if (b < PB_WM) { do_transpose_h(Wm, wmt, DIN, HID, b & 31, b >> 5, t); return; }
    b -= PB_WM;
    if (b < PB_W2) { do_transpose_h(W2, w2t, 2 * DIN, HID, b & 31, b >> 5, t); return; }
    b -= PB_W2;
    {
        const int z = b >> 9;            // 512 tiles per batch (32 x 16)
        const int r = b & 511;
        do_transpose_h(mem + (size_t)z * LMEM * DIN, memt + (size_t)z * LMEM * DIN,
                       LMEM, DIN, r & 31, r >> 5, t);
    }
}

// ---------------- masked softmax: f32 logits in, fp16 probs out -----------
__global__ void softmax_w(const float* __restrict__ att, __half* __restrict__ attp,
                          const float* __restrict__ mask)
{
    const int gw = blockIdx.x * 8 + (threadIdx.x >> 5);
    const int lane = threadIdx.x & 31;
    const float4* p4 = (const float4*)(att + (size_t)gw * LMEM);
    const float4* m4 = (const float4*)(mask + (size_t)(gw >> 11) * LMEM);

    float4 v[4];
    float mx = -3.4e38f;
#pragma unroll
    for (int q = 0; q < 4; q++) {
        float4 a = p4[lane + q * 32];
        float4 mm = m4[lane + q * 32];
        a.x -= 1e30f * (1.0f - mm.x);
        a.y -= 1e30f * (1.0f - mm.y);
        a.z -= 1e30f * (1.0f - mm.z);
        a.w -= 1e30f * (1.0f - mm.w);
        v[q] = a;
        mx = fmaxf(mx, fmaxf(fmaxf(a.x, a.y), fmaxf(a.z, a.w)));
    }
#pragma unroll
    for (int s = 16; s > 0; s >>= 1)
        mx = fmaxf(mx, __shfl_xor_sync(0xffffffffu, mx, s));
    float sum = 0.0f;
#pragma unroll
    for (int q = 0; q < 4; q++) {
        v[q].x = __expf(v[q].x - mx);
        v[q].y = __expf(v[q].y - mx);
        v[q].z = __expf(v[q].z - mx);
        v[q].w = __expf(v[q].w - mx);
        sum += v[q].x + v[q].y + v[q].z + v[q].w;
    }
#pragma unroll
    for (int s = 16; s > 0; s >>= 1)
        sum += __shfl_xor_sync(0xffffffffu, sum, s);
    const float inv = 1.0f / sum;
    uint2* o2 = (uint2*)(attp + (size_t)gw * LMEM);   // 8B = 4 halves
#pragma unroll
    for (int q = 0; q < 4; q++) {
        o2[lane + q * 32] = make_uint2(
            h2u(__floats2half2_rn(v[q].x * inv, v[q].y * inv)),
            h2u(__floats2half2_rn(v[q].z * inv, v[q].w * inv)));
    }
}

// ---------------- launch ---------------------------------------------------
extern "C" void kernel_launch(void* const* d_in, const int* in_sizes, int n_in,
                              void* d_out, int out_size)
{
    const float* x    = (const float*)d_in[0];
    const float* mem  = (const float*)d_in[1];
    const float* mask = (const float*)d_in[2];
    const float* W1   = (const float*)d_in[3];
    const float* b1   = (const float*)d_in[4];
    const float* Wm   = (const float*)d_in[5];
    const float* bm   = (const float*)d_in[6];
    const float* W2   = (const float*)d_in[7];
    const float* b2   = (const float*)d_in[8];
    float* out = (float*)d_out;

    __half *p_id, *p_md, *p_attp, *p_oo, *p_w1t, *p_wmt, *p_w2t, *p_memt, *p_xh, *p_memh;
    float *p_att;
    cudaGetSymbolAddress((void**)&p_id,   g_input_dot);
    cudaGetSymbolAddress((void**)&p_md,   g_memory_dot);
    cudaGetSymbolAddress((void**)&p_att,  g_att);
    cudaGetSymbolAddress((void**)&p_attp, g_attp);
    cudaGetSymbolAddress((void**)&p_oo,   g_out_one);
    cudaGetSymbolAddress((void**)&p_w1t,  g_w1t);
    cudaGetSymbolAddress((void**)&p_wmt,  g_wmt);
    cudaGetSymbolAddress((void**)&p_w2t,  g_w2t);
    cudaGetSymbolAddress((void**)&p_memt, g_memt);
    cudaGetSymbolAddress((void**)&p_xh,   g_xh);
    cudaGetSymbolAddress((void**)&p_memh, g_memh);

    cudaFuncSetAttribute(mma_gemm<ACT_RELU, false, false>,
                         cudaFuncAttributeMaxDynamicSharedMemorySize, GEMM_SMEM);
    cudaFuncSetAttribute(mma_gemm<ACT_NONE, false, true>,
                         cudaFuncAttributeMaxDynamicSharedMemorySize, GEMM_SMEM);
    cudaFuncSetAttribute(mma_gemm<ACT_NONE, false, false>,
                         cudaFuncAttributeMaxDynamicSharedMemorySize, GEMM_SMEM);
    cudaFuncSetAttribute(mma_gemm<ACT_GATE, true, true>,
                         cudaFuncAttributeMaxDynamicSharedMemorySize, GEMM_SMEM);

    // 0) fused operand conditioning + mem passthrough, ONE launch
    prep_k<<<PREP_BLOCKS, 256>>>(x, mem, W1, Wm, W2,
                                 p_xh, p_memh, p_w1t, p_wmt, p_w2t, p_memt,
                                 out + (size_t)NB * LDQ * HID);

    // 1) input_dot = relu(x @ W1 + b1)            [16384,1024] K=1024, half out
    mma_gemm<ACT_RELU, false, false><<<dim3(HID / 128, (NB * LDQ) / 128, 1), 128, GEMM_SMEM>>>(
        p_xh, p_xh, p_w1t, b1, p_id, DIN, DIN, DIN, DIN, HID, 0, 0, 0, 1.0f);

    // 2) memory_dot = relu(mem @ Wm + bm)         [4096,1024]  K=1024, half out
    mma_gemm<ACT_RELU, false, false><<<dim3(HID / 128, (NB * LMEM) / 128, 1), 128, GEMM_SMEM>>>(
        p_memh, p_memh, p_wmt, bm, p_md, DIN, DIN, DIN, DIN, HID, 0, 0, 0, 1.0f);

    // 3) att = input_dot @ memory_dot^T / 32      [8][2048,512] K=1024, F32 out
    mma_gemm<ACT_NONE, false, true><<<dim3(LMEM / 128, LDQ / 128, NB), 128, GEMM_SMEM>>>(
        p_id, p_id, p_md, nullptr, p_att, HID, HID, HID, HID, LMEM,
        (long long)LDQ * HID, (long long)LMEM * HID, (long long)LDQ * LMEM, 1.0f / 32.0f);

    // 4) masked softmax: f32 logits -> fp16 probabilities
    softmax_w<<<(NB * LDQ) / 8, 256>>>(p_att, p_attp, mask);

    // 5) out_one = att @ mem                       [8][2048,1024] K=512, half out
    mma_gemm<ACT_NONE, false, false><<<dim3(DIN / 128, LDQ / 128, NB), 128, GEMM_SMEM>>>(
        p_attp, p_attp, p_memt, nullptr, p_oo, LMEM, LMEM, LMEM, LMEM, DIN,
        (long long)LDQ * LMEM, (long long)DIN * LMEM, (long long)LDQ * DIN, 1.0f);

    // 6) out = gate(concat(x, out_one) @ W2 + b2)  [16384,1024] K=2048, F32 out
    mma_gemm<ACT_GATE, true, true><<<dim3(HID / 128, (NB * LDQ) / 128, 1), 128, GEMM_SMEM>>>(
        p_xh, p_oo, p_w2t, b2, out, 2 * DIN, DIN, DIN, 2 * DIN, HID, 0, 0, 0, 1.0f);
}

// round 14
// speedup vs baseline: 1.1285x; 1.1285x over previous
#include <cuda_runtime.h>
#include <cuda_fp16.h>
#include <cstdint>
#include <math.h>

#define NB   8
#define LDQ  2048
#define LMEM 512
#define DIN  1024
#define HID  1024

// ---------------- scratch (__device__ globals; no allocations allowed) ----
__device__ __half g_input_dot[(size_t)NB * LDQ * HID];   // 32 MB
__device__ __half g_memory_dot[(size_t)NB * LMEM * HID]; // 8 MB
__device__ float  g_att[(size_t)NB * LDQ * LMEM];        // 32 MB (f32 logits)
__device__ __half g_attp[(size_t)NB * LDQ * LMEM];       // 16 MB (fp16 probs)
__device__ __half g_out_one[(size_t)NB * LDQ * DIN];     // 32 MB
__device__ __half g_w1t[(size_t)DIN * HID];              // 2 MB
__device__ __half g_wmt[(size_t)DIN * HID];              // 2 MB
__device__ __half g_w2t[(size_t)2 * DIN * HID];          // 4 MB
__device__ __half g_memt[(size_t)NB * DIN * LMEM];       // 8 MB
__device__ __half g_xh[(size_t)NB * LDQ * DIN];          // 32 MB (x as fp16)
__device__ __half g_memh[(size_t)NB * LMEM * DIN];       // 8 MB (mem as fp16)

enum { ACT_NONE = 0, ACT_RELU = 1, ACT_GATE = 2 };

// ---------------- helpers --------------------------------------------------
__device__ __forceinline__ uint32_t smem_u32(const void* p) {
    uint32_t a;
    asm("{ .reg .u64 t; cvta.to.shared.u64 t, %1; cvt.u32.u64 %0, t; }" : "=r"(a) : "l"(p));
    return a;
}
// bit-cast __half2 -> u32 (this toolchain lacks __half2_as_uint)
__device__ __forceinline__ uint32_t h2u(__half2 h) {
    __half2_raw r = *reinterpret_cast<__half2_raw*>(&h);
    return (uint32_t)r.x | ((uint32_t)r.y << 16);
}

#define CP16(dst, src) \
    asm volatile("cp.async.cg.shared.global [%0], [%1], 16;" :: "r"(dst), "l"(src))
#define CP_COMMIT() asm volatile("cp.async.commit_group;")
#define CP_WAIT1()  asm volatile("cp.async.wait_group 1;")

#define LDSM4(r0, r1, r2, r3, addr) \
    asm volatile("ldmatrix.sync.aligned.m8n8.x4.shared.b16 {%0,%1,%2,%3}, [%4];" \
        : "=r"(r0), "=r"(r1), "=r"(r2), "=r"(r3) : "r"(addr))

// fp16 tensor-core mma, fp32 accumulate
__device__ __forceinline__ void mma_f16(float* d, const uint32_t* a, const uint32_t* b) {
    asm volatile(
        "mma.sync.aligned.m16n8k16.row.col.f32.f16.f16.f32 "
        "{%0,%1,%2,%3}, {%4,%5,%6,%7}, {%8,%9}, {%0,%1,%2,%3};"
        : "+f"(d[0]), "+f"(d[1]), "+f"(d[2]), "+f"(d[3])
        : "r"(a[0]), "r"(a[1]), "r"(a[2]), "r"(a[3]), "r"(b[0]), "r"(b[1]));
}

// ---------------- fp16 mma.sync NT GEMM: C[M,N] = A[M,K] * B[N,K]^T -------
// BM=128, BN=128, BK=64 halves. 256 threads, 8 warps (2 row x 4 col), warp
// tile 64x32 -> acc 64 regs/thread, ~120 total, 2 CTAs/SM under the 128-reg
// cap => 16 warps/SM = 4 warps/SMSP (every prior round had only 2 — the
// never-tested variable). 3-stage cp.async pipeline, one barrier per iter,
// R12's proven per-ks interleave (hand double-buffering regressed twice).
// Smem rows: 64 halves data + 8 pad = 36 words (144 B); conflict-free
// ({36r mod 32 | r=0..7} covers all banks with word 0..3).
static constexpr int AROW_W = 36;                  // words per A/B smem row
static constexpr int ASZ = 128 * AROW_W;           // words per A stage
static constexpr int BSZ = 128 * AROW_W;           // words per B stage
static constexpr int STAGES = 3;
static constexpr int GEMM_SMEM = (ASZ + BSZ) * STAGES * 4;   // 110592 B

// Separate K indices: ka for the (possibly switched) A source, kb for B.
// 256 threads: each loads 4 x 16B chunks of A and 4 of B.
__device__ __forceinline__ void load_tile(
    uint32_t sb, int s, const __half* __restrict__ Ap, const __half* __restrict__ Bp,
    int m0, int n0, int ka, int kb, int lda, int ldb, int t)
{
    const uint32_t as = sb + s * (ASZ * 4);
    const uint32_t bs = sb + STAGES * (ASZ * 4) + s * (BSZ * 4);
    const int r  = t >> 3;            // 0..31
    const int c4 = (t & 7) * 4;       // word offset in row (16B chunks, 8/row)
    const __half* ag = &Ap[(size_t)(m0 + r) * lda + ka + (t & 7) * 8];
#pragma unroll
    for (int q = 0; q < 4; q++)
        CP16(as + ((r + q * 32) * AROW_W + c4) * 4, ag + (size_t)(q * 32) * lda);
    const __half* bg = &Bp[(size_t)(n0 + r) * ldb + kb + (t & 7) * 8];
#pragma unroll
    for (int q = 0; q < 4; q++)
        CP16(bs + ((r + q * 32) * AROW_W + c4) * 4, bg + (size_t)(q * 32) * ldb);
    CP_COMMIT();
}

template <int ACT, bool DUALA, bool OUTF32>
__global__ void __launch_bounds__(256, 2)
mma_gemm(const __half* __restrict__ A1, const __half* __restrict__ A2,
         const __half* __restrict__ B, const float* __restrict__ bias,
         void* __restrict__ Cv,
         int K, int Ksplit, int lda, int ldb, int ldc,
         long long sA, long long sB, long long sC, float scale)
{
    extern __shared__ float sm[];
    const uint32_t sb = smem_u32(sm);

    const int t    = threadIdx.x;
    const int wid  = t >> 5;
    const int lane = t & 31;
    const int gid  = lane >> 2;      // 0..7
    const int tig  = lane & 3;       // 0..3
    const int z = blockIdx.z;
    A1 += (size_t)z * sA;
    A2 += (size_t)z * sA;
    B  += (size_t)z * sB;
    const int m0 = blockIdx.y * 128;
    const int n0 = blockIdx.x * 128;

    const int NI = K >> 6;           // BK = 64 halves

    const int mb = (wid >> 2) * 64;   // warp row offset (2x4 warp grid)
    const int nb = (wid & 3) * 32;    // warp col offset

    // ldmatrix per-lane base addresses (bytes); stage/mi/ks offsets added later.
    const uint32_t a_lm = sb
        + (((mb + (lane & 15)) * AROW_W + (lane >> 4) * 4) << 2);
    const uint32_t b_lm = sb + STAGES * (ASZ * 4)
        + (((nb + (lane & 7) + ((lane >> 4) << 3)) * AROW_W + ((lane >> 3) & 1) * 4) << 2);

    // prologue: prefetch STAGES-1 = 2 stages
#pragma unroll
    for (int s = 0; s < 2; s++) {
        const int k0 = s * 64;
        const __half* Ap = A1;
        int ka = k0;
        if (DUALA && k0 >= Ksplit) { Ap = A2; ka = k0 - Ksplit; }
        load_tile(sb, s, Ap, B, m0, n0, ka, k0, lda, ldb, t);
    }

    float acc[4][4][4];
#pragma unroll
    for (int i = 0; i < 4; i++)
#pragma unroll
        for (int j = 0; j < 4; j++)
#pragma unroll
            for (int q = 0; q < 4; q++) acc[i][j][q] = 0.0f;

    for (int i = 0; i < NI; i++) {
        CP_WAIT1();
        __syncthreads();   // compute of iter i-1 done on all warps ->
                           // writing stage (i+2)%3 == (i-1)%3 below is WAR-safe.

        const int s = i % 3;
        const uint32_t a_s = a_lm + s * (ASZ * 4);
        const uint32_t b_s = b_lm + s * (BSZ * 4);

#pragma unroll
        for (int ks = 0; ks < 4; ks++) {          // four k16 steps (+32 B each)
            uint32_t af[4][4];
#pragma unroll
            for (int mi = 0; mi < 4; mi++)
                LDSM4(af[mi][0], af[mi][1], af[mi][2], af[mi][3],
                      a_s + mi * (16 * AROW_W * 4) + ks * 32);
            uint32_t bf[4][2];
#pragma unroll
            for (int g = 0; g < 2; g++)
                LDSM4(bf[2 * g][0], bf[2 * g][1], bf[2 * g + 1][0], bf[2 * g + 1][1],
                      b_s + g * (16 * AROW_W * 4) + ks * 32);
#pragma unroll
            for (int mi = 0; mi < 4; mi++)
#pragma unroll
                for (int nj = 0; nj < 4; nj++)
                    mma_f16(acc[mi][nj], af[mi], bf[nj]);
        }

        const int nx = i + 2;
        if (nx < NI) {
            const int k0 = nx * 64;
            const __half* Ap = A1;
            int ka = k0;
            if (DUALA && k0 >= Ksplit) { Ap = A2; ka = k0 - Ksplit; }
            load_tile(sb, nx % 3, Ap, B, m0, n0, ka, k0, lda, ldb, t);
        } else {
            CP_COMMIT();   // keep group count in lockstep for CP_WAIT1
        }
    }

    // ---- epilogue ----
    float*  Cf = (float*)Cv  + (size_t)z * sC;
    __half* Ch = (__half*)Cv + (size_t)z * sC;
#pragma unroll
    for (int mi = 0; mi < 4; mi++) {
        const int r0 = m0 + mb + mi * 16 + gid;
#pragma unroll
        for (int nj = 0; nj < 4; nj++) {
            const int c0 = n0 + nb + nj * 8 + tig * 2;
            float v[4];
#pragma unroll
            for (int q = 0; q < 4; q++) v[q] = acc[mi][nj][q] * scale;
            if (ACT != ACT_NONE) {
                const float bb0 = __ldg(&bias[c0]);
                const float bb1 = __ldg(&bias[c0 + 1]);
                v[0] += bb0; v[1] += bb1; v[2] += bb0; v[3] += bb1;
            }
#pragma unroll
            for (int q = 0; q < 4; q++) {
                if (ACT == ACT_RELU) v[q] = fmaxf(v[q], 0.0f);
                if (ACT == ACT_GATE) {
                    const float sg = 1.0f / (1.0f + expf(-v[q]));
                    v[q] = sg * tanhf(v[q]);
                }
            }
            if (OUTF32) {
                *(float2*)&Cf[(size_t)r0 * ldc + c0]       = make_float2(v[0], v[1]);
                *(float2*)&Cf[(size_t)(r0 + 8) * ldc + c0] = make_float2(v[2], v[3]);
            } else {
                *(__half2*)&Ch[(size_t)r0 * ldc + c0] =
                    __floats2half2_rn(v[0], v[1]);
                *(__half2*)&Ch[(size_t)(r0 + 8) * ldc + c0] =
                    __floats2half2_rn(v[2], v[3]);
            }
        }
    }
}

// ---------------- fused prep: transposes + fp16 converts + mem passthrough -
__device__ __forceinline__ void do_transpose_h(
    const float* __restrict__ src, __half* __restrict__ dst,
    int R, int C, int tX, int tY, int t)
{
    __shared__ float tile[32][33];
    const int lx = t & 31, ly = t >> 5;   // 32 x 8
    const int x = tX * 32 + lx;
    const int y0 = tY * 32;
#pragma unroll
    for (int i = ly; i < 32; i += 8)
        tile[i][lx] = src[(size_t)(y0 + i) * C + x];
    __syncthreads();
    const int xo = tY * 32 + lx;
    const int yo0 = tX * 32;
#pragma unroll
    for (int i = ly; i < 32; i += 8)
        dst[(size_t)(yo0 + i) * R + xo] = __float2half_rn(tile[lx][i]);
}

static constexpr int PB_RX   = 16384;   // x -> half     (16M floats)
static constexpr int PB_RM   = 4096;    // mem -> half   (4M floats)
static constexpr int PB_CP   = 4096;    // mem -> out tail (f32 copy, 1M float4)
static constexpr int PB_W1   = 1024;    // W1t
static constexpr int PB_WM   = 1024;    // Wmt
static constexpr int PB_W2   = 2048;    // W2t
static constexpr int PB_MT   = 4096;    // memt (z=8)
static constexpr int PREP_BLOCKS =
    PB_RX + PB_RM + PB_CP + PB_W1 + PB_WM + PB_W2 + PB_MT;

__global__ void __launch_bounds__(256)
prep_k(const float* __restrict__ x, const float* __restrict__ mem,
       const float* __restrict__ W1, const float* __restrict__ Wm,
       const float* __restrict__ W2,
       __half* __restrict__ xh, __half* __restrict__ memh,
       __half* __restrict__ w1t, __half* __restrict__ wmt,
       __half* __restrict__ w2t, __half* __restrict__ memt,
       float* __restrict__ out_tail)
{
    int b = blockIdx.x;
    const int t = threadIdx.x;
    if (b < PB_RX) {
        const int i = b * 256 + t;
        float4 v = ((const float4*)x)[i];
        ((uint2*)xh)[i] = make_uint2(
            h2u(__floats2half2_rn(v.x, v.y)),
            h2u(__floats2half2_rn(v.z, v.w)));
        return;
    }
    b -= PB_RX;
    if (b < PB_RM) {
        const int i = b * 256 + t;
        float4 v = ((const float4*)mem)[i];
        ((uint2*)memh)[i] = make_uint2(
            h2u(__floats2half2_rn(v.x, v.y)),
            h2u(__floats2half2_rn(v.z, v.w)));
        return;
    }
    b -= PB_RM;
    if (b < PB_CP) {                 // exact mem passthrough to output tuple[1]
        const int i = b * 256 + t;
        ((float4*)out_tail)[i] = ((const float4*)mem)[i];
        return;
    }
    b -= PB_CP;
    if (b < PB_W1) { do_transpose_h(W1, w1t, DIN, HID, b & 31, b >> 5, t); return; }
    b -= PB_W1;
    if (b < PB_WM) { do_transpose_h(Wm, wmt, DIN, HID, b & 31, b >> 5, t); return; }
    b -= PB_WM;
    if (b < PB_W2) { do_transpose_h(W2, w2t, 2 * DIN, HID, b & 31, b >> 5, t); return; }
    b -= PB_W2;
    {
        const int z = b >> 9;            // 512 tiles per batch (32 x 16)
        const int r = b & 511;
        do_transpose_h(mem + (size_t)z * LMEM * DIN, memt + (size_t)z * LMEM * DIN,
                       LMEM, DIN, r & 31, r >> 5, t);
    }
}

// ---------------- masked softmax: f32 logits in, fp16 probs out -----------
__global__ void softmax_w(const float* __restrict__ att, __half* __restrict__ attp,
                          const float* __restrict__ mask)
{
    const int gw = blockIdx.x * 8 + (threadIdx.x >> 5);
    const int lane = threadIdx.x & 31;
    const float4* p4 = (const float4*)(att + (size_t)gw * LMEM);
    const float4* m4 = (const float4*)(mask + (size_t)(gw >> 11) * LMEM);

    float4 v[4];
    float mx = -3.4e38f;
#pragma unroll
    for (int q = 0; q < 4; q++) {
        float4 a = p4[lane + q * 32];
        float4 mm = m4[lane + q * 32];
        a.x -= 1e30f * (1.0f - mm.x);
        a.y -= 1e30f * (1.0f - mm.y);
        a.z -= 1e30f * (1.0f - mm.z);
        a.w -= 1e30f * (1.0f - mm.w);
        v[q] = a;
        mx = fmaxf(mx, fmaxf(fmaxf(a.x, a.y), fmaxf(a.z, a.w)));
    }
#pragma unroll
    for (int s = 16; s > 0; s >>= 1)
        mx = fmaxf(mx, __shfl_xor_sync(0xffffffffu, mx, s));
    float sum = 0.0f;
#pragma unroll
    for (int q = 0; q < 4; q++) {
        v[q].x = __expf(v[q].x - mx);
        v[q].y = __expf(v[q].y - mx);
        v[q].z = __expf(v[q].z - mx);
        v[q].w = __expf(v[q].w - mx);
        sum += v[q].x + v[q].y + v[q].z + v[q].w;
    }
#pragma unroll
    for (int s = 16; s > 0; s >>= 1)
        sum += __shfl_xor_sync(0xffffffffu, sum, s);
    const float inv = 1.0f / sum;
    uint2* o2 = (uint2*)(attp + (size_t)gw * LMEM);   // 8B = 4 halves
#pragma unroll
    for (int q = 0; q < 4; q++) {
        o2[lane + q * 32] = make_uint2(
            h2u(__floats2half2_rn(v[q].x * inv, v[q].y * inv)),
            h2u(__floats2half2_rn(v[q].z * inv, v[q].w * inv)));
    }
}

// ---------------- launch ---------------------------------------------------
extern "C" void kernel_launch(void* const* d_in, const int* in_sizes, int n_in,
                              void* d_out, int out_size)
{
    const float* x    = (const float*)d_in[0];
    const float* mem  = (const float*)d_in[1];
    const float* mask = (const float*)d_in[2];
    const float* W1   = (const float*)d_in[3];
    const float* b1   = (const float*)d_in[4];
    const float* Wm   = (const float*)d_in[5];
    const float* bm   = (const float*)d_in[6];
    const float* W2   = (const float*)d_in[7];
    const float* b2   = (const float*)d_in[8];
    float* out = (float*)d_out;

    __half *p_id, *p_md, *p_attp, *p_oo, *p_w1t, *p_wmt, *p_w2t, *p_memt, *p_xh, *p_memh;
    float *p_att;
    cudaGetSymbolAddress((void**)&p_id,   g_input_dot);
    cudaGetSymbolAddress((void**)&p_md,   g_memory_dot);
    cudaGetSymbolAddress((void**)&p_att,  g_att);
    cudaGetSymbolAddress((void**)&p_attp, g_attp);
    cudaGetSymbolAddress((void**)&p_oo,   g_out_one);
    cudaGetSymbolAddress((void**)&p_w1t,  g_w1t);
    cudaGetSymbolAddress((void**)&p_wmt,  g_wmt);
    cudaGetSymbolAddress((void**)&p_w2t,  g_w2t);
    cudaGetSymbolAddress((void**)&p_memt, g_memt);
    cudaGetSymbolAddress((void**)&p_xh,   g_xh);
    cudaGetSymbolAddress((void**)&p_memh, g_memh);

    cudaFuncSetAttribute(mma_gemm<ACT_RELU, false, false>,
                         cudaFuncAttributeMaxDynamicSharedMemorySize, GEMM_SMEM);
    cudaFuncSetAttribute(mma_gemm<ACT_NONE, false, true>,
                         cudaFuncAttributeMaxDynamicSharedMemorySize, GEMM_SMEM);
    cudaFuncSetAttribute(mma_gemm<ACT_NONE, false, false>,
                         cudaFuncAttributeMaxDynamicSharedMemorySize, GEMM_SMEM);
    cudaFuncSetAttribute(mma_gemm<ACT_GATE, true, true>,
                         cudaFuncAttributeMaxDynamicSharedMemorySize, GEMM_SMEM);

    // 0) fused operand conditioning + mem passthrough, ONE launch
    prep_k<<<PREP_BLOCKS, 256>>>(x, mem, W1, Wm, W2,
                                 p_xh, p_memh, p_w1t, p_wmt, p_w2t, p_memt,
                                 out + (size_t)NB * LDQ * HID);

    // 1) input_dot = relu(x @ W1 + b1)            [16384,1024] K=1024, half out
    mma_gemm<ACT_RELU, false, false><<<dim3(HID / 128, (NB * LDQ) / 128, 1), 256, GEMM_SMEM>>>(
        p_xh, p_xh, p_w1t, b1, p_id, DIN, DIN, DIN, DIN, HID, 0, 0, 0, 1.0f);

    // 2) memory_dot = relu(mem @ Wm + bm)         [4096,1024]  K=1024, half out
    mma_gemm<ACT_RELU, false, false><<<dim3(HID / 128, (NB * LMEM) / 128, 1), 256, GEMM_SMEM>>>(
        p_memh, p_memh, p_wmt, bm, p_md, DIN, DIN, DIN, DIN, HID, 0, 0, 0, 1.0f);

    // 3) att = input_dot @ memory_dot^T / 32      [8][2048,512] K=1024, F32 out
    mma_gemm<ACT_NONE, false, true><<<dim3(LMEM / 128, LDQ / 128, NB), 256, GEMM_SMEM>>>(
        p_id, p_id, p_md, nullptr, p_att, HID, HID, HID, HID, LMEM,
        (long long)LDQ * HID, (long long)LMEM * HID, (long long)LDQ * LMEM, 1.0f / 32.0f);

    // 4) masked softmax: f32 logits -> fp16 probabilities
    softmax_w<<<(NB * LDQ) / 8, 256>>>(p_att, p_attp, mask);

    // 5) out_one = att @ mem                       [8][2048,1024] K=512, half out
    mma_gemm<ACT_NONE, false, false><<<dim3(DIN / 128, LDQ / 128, NB), 256, GEMM_SMEM>>>(
        p_attp, p_attp, p_memt, nullptr, p_oo, LMEM, LMEM, LMEM, LMEM, DIN,
        (long long)LDQ * LMEM, (long long)DIN * LMEM, (long long)LDQ * DIN, 1.0f);

    // 6) out = gate(concat(x, out_one) @ W2 + b2)  [16384,1024] K=2048, F32 out
    mma_gemm<ACT_GATE, true, true><<<dim3(HID / 128, (NB * LDQ) / 128, 1), 256, GEMM_SMEM>>>(
        p_xh, p_oo, p_w2t, b2, out, 2 * DIN, DIN, DIN, 2 * DIN, HID, 0, 0, 0, 1.0f);
}

// round 15
// speedup vs baseline: 1.1401x; 1.0103x over previous
#include <cuda_runtime.h>
#include <cuda_fp16.h>
#include <cstdint>
#include <math.h>

#define NB   8
#define LDQ  2048
#define LMEM 512
#define DIN  1024
#define HID  1024

// ---------------- scratch (__device__ globals; no allocations allowed) ----
__device__ __half g_input_dot[(size_t)NB * LDQ * HID];   // 32 MB
__device__ __half g_memory_dot[(size_t)NB * LMEM * HID]; // 8 MB
__device__ float  g_att[(size_t)NB * LDQ * LMEM];        // 32 MB (f32 logits)
__device__ __half g_attp[(size_t)NB * LDQ * LMEM];       // 16 MB (fp16 probs)
__device__ __half g_out_one[(size_t)NB * LDQ * DIN];     // 32 MB
__device__ __half g_w1t[(size_t)DIN * HID];              // 2 MB
__device__ __half g_wmt[(size_t)DIN * HID];              // 2 MB
__device__ __half g_w2t[(size_t)2 * DIN * HID];          // 4 MB
__device__ __half g_memt[(size_t)NB * DIN * LMEM];       // 8 MB
__device__ __half g_xh[(size_t)NB * LDQ * DIN];          // 32 MB (x as fp16)
__device__ __half g_memh[(size_t)NB * LMEM * DIN];       // 8 MB (mem as fp16)

enum { ACT_NONE = 0, ACT_RELU = 1, ACT_GATE = 2 };

// ---------------- helpers --------------------------------------------------
__device__ __forceinline__ uint32_t smem_u32(const void* p) {
    uint32_t a;
    asm("{ .reg .u64 t; cvta.to.shared.u64 t, %1; cvt.u32.u64 %0, t; }" : "=r"(a) : "l"(p));
    return a;
}
// bit-cast __half2 -> u32 (this toolchain lacks __half2_as_uint)
__device__ __forceinline__ uint32_t h2u(__half2 h) {
    __half2_raw r = *reinterpret_cast<__half2_raw*>(&h);
    return (uint32_t)r.x | ((uint32_t)r.y << 16);
}

#define CP16(dst, src) \
    asm volatile("cp.async.cg.shared.global [%0], [%1], 16;" :: "r"(dst), "l"(src))
#define CP_COMMIT() asm volatile("cp.async.commit_group;")
#define CP_WAIT1()  asm volatile("cp.async.wait_group 1;")

#define LDSM4(r0, r1, r2, r3, addr) \
    asm volatile("ldmatrix.sync.aligned.m8n8.x4.shared.b16 {%0,%1,%2,%3}, [%4];" \
        : "=r"(r0), "=r"(r1), "=r"(r2), "=r"(r3) : "r"(addr))

// fp16 tensor-core mma, fp32 accumulate
__device__ __forceinline__ void mma_f16(float* d, const uint32_t* a, const uint32_t* b) {
    asm volatile(
        "mma.sync.aligned.m16n8k16.row.col.f32.f16.f16.f32 "
        "{%0,%1,%2,%3}, {%4,%5,%6,%7}, {%8,%9}, {%0,%1,%2,%3};"
        : "+f"(d[0]), "+f"(d[1]), "+f"(d[2]), "+f"(d[3])
        : "r"(a[0]), "r"(a[1]), "r"(a[2]), "r"(a[3]), "r"(b[0]), "r"(b[1]));
}

// ---------------- fp16 mma.sync NT GEMM: C[M,N] = A[M,K] * B[N,K]^T -------
// BM=128, BN=128, BK=64 halves. 256 threads, 8 warps (2x4), warp tile 64x32.
// 2 CTAs/SM (128 regs) = 4 warps/SMSP. 3-stage cp.async pipeline, one barrier
// per iteration. Engine efficiency plateaus at ~52% tensor (legacy-HMMA issue
// ceiling — measured invariant across occupancy/BK/schedule); this round cuts
// launch/tail/traffic overheads instead.
// FUSED: blocks with blockIdx.y >= yspl switch to a second problem's pointer
// set (used to merge GEMM1+GEMM2 into one launch, removing GEMM2's 0.86-wave
// tail).
static constexpr int AROW_W = 36;                  // words per A/B smem row
static constexpr int ASZ = 128 * AROW_W;           // words per A stage
static constexpr int BSZ = 128 * AROW_W;           // words per B stage
static constexpr int STAGES = 3;
static constexpr int GEMM_SMEM = (ASZ + BSZ) * STAGES * 4;   // 110592 B

// Separate K indices: ka for the (possibly switched) A source, kb for B.
__device__ __forceinline__ void load_tile(
    uint32_t sb, int s, const __half* __restrict__ Ap, const __half* __restrict__ Bp,
    int m0, int n0, int ka, int kb, int lda, int ldb, int t)
{
    const uint32_t as = sb + s * (ASZ * 4);
    const uint32_t bs = sb + STAGES * (ASZ * 4) + s * (BSZ * 4);
    const int r  = t >> 3;            // 0..31
    const int c4 = (t & 7) * 4;       // word offset in row (16B chunks, 8/row)
    const __half* ag = &Ap[(size_t)(m0 + r) * lda + ka + (t & 7) * 8];
#pragma unroll
    for (int q = 0; q < 4; q++)
        CP16(as + ((r + q * 32) * AROW_W + c4) * 4, ag + (size_t)(q * 32) * lda);
    const __half* bg = &Bp[(size_t)(n0 + r) * ldb + kb + (t & 7) * 8];
#pragma unroll
    for (int q = 0; q < 4; q++)
        CP16(bs + ((r + q * 32) * AROW_W + c4) * 4, bg + (size_t)(q * 32) * ldb);
    CP_COMMIT();
}

template <int ACT, bool DUALA, bool OUTF32, bool FUSED>
__global__ void __launch_bounds__(256, 2)
mma_gemm(const __half* __restrict__ A1, const __half* __restrict__ A2,
         const __half* __restrict__ B, const float* __restrict__ bias,
         void* __restrict__ Cv,
         int K, int Ksplit, int lda, int ldb, int ldc,
         long long sA, long long sB, long long sC, float scale,
         const __half* __restrict__ A1b, const __half* __restrict__ Bb,
         const float* __restrict__ biasb, void* __restrict__ Cvb, int yspl)
{
    extern __shared__ float sm[];
    const uint32_t sb = smem_u32(sm);

    const int t    = threadIdx.x;
    const int wid  = t >> 5;
    const int lane = t & 31;
    const int gid  = lane >> 2;      // 0..7
    const int tig  = lane & 3;       // 0..3
    const int z = blockIdx.z;

    int by = blockIdx.y;
    if (FUSED && by >= yspl) {       // second fused problem (GEMM2)
        by -= yspl;
        A1 = A1b; A2 = A1b; B = Bb; bias = biasb; Cv = Cvb;
    }
    A1 += (size_t)z * sA;
    A2 += (size_t)z * sA;
    B  += (size_t)z * sB;
    const int m0 = by * 128;
    const int n0 = blockIdx.x * 128;

    const int NI = K >> 6;           // BK = 64 halves

    const int mb = (wid >> 2) * 64;   // warp row offset (2x4 warp grid)
    const int nb = (wid & 3) * 32;    // warp col offset

    // ldmatrix per-lane base addresses (bytes); stage/mi/ks offsets added later.
    const uint32_t a_lm = sb
        + (((mb + (lane & 15)) * AROW_W + (lane >> 4) * 4) << 2);
    const uint32_t b_lm = sb + STAGES * (ASZ * 4)
        + (((nb + (lane & 7) + ((lane >> 4) << 3)) * AROW_W + ((lane >> 3) & 1) * 4) << 2);

    // prologue: prefetch STAGES-1 = 2 stages
#pragma unroll
    for (int s = 0; s < 2; s++) {
        const int k0 = s * 64;
        const __half* Ap = A1;
        int ka = k0;
        if (DUALA && k0 >= Ksplit) { Ap = A2; ka = k0 - Ksplit; }
        load_tile(sb, s, Ap, B, m0, n0, ka, k0, lda, ldb, t);
    }

    float acc[4][4][4];
#pragma unroll
    for (int i = 0; i < 4; i++)
#pragma unroll
        for (int j = 0; j < 4; j++)
#pragma unroll
            for (int q = 0; q < 4; q++) acc[i][j][q] = 0.0f;

    for (int i = 0; i < NI; i++) {
        CP_WAIT1();
        __syncthreads();   // compute of iter i-1 done on all warps ->
                           // writing stage (i+2)%3 == (i-1)%3 below is WAR-safe.

        const int s = i % 3;
        const uint32_t a_s = a_lm + s * (ASZ * 4);
        const uint32_t b_s = b_lm + s * (BSZ * 4);

#pragma unroll
        for (int ks = 0; ks < 4; ks++) {          // four k16 steps (+32 B each)
            uint32_t af[4][4];
#pragma unroll
            for (int mi = 0; mi < 4; mi++)
                LDSM4(af[mi][0], af[mi][1], af[mi][2], af[mi][3],
                      a_s + mi * (16 * AROW_W * 4) + ks * 32);
            uint32_t bf[4][2];
#pragma unroll
            for (int g = 0; g < 2; g++)
                LDSM4(bf[2 * g][0], bf[2 * g][1], bf[2 * g + 1][0], bf[2 * g + 1][1],
                      b_s + g * (16 * AROW_W * 4) + ks * 32);
#pragma unroll
            for (int mi = 0; mi < 4; mi++)
#pragma unroll
                for (int nj = 0; nj < 4; nj++)
                    mma_f16(acc[mi][nj], af[mi], bf[nj]);
        }

        const int nx = i + 2;
        if (nx < NI) {
            const int k0 = nx * 64;
            const __half* Ap = A1;
            int ka = k0;
            if (DUALA && k0 >= Ksplit) { Ap = A2; ka = k0 - Ksplit; }
            load_tile(sb, nx % 3, Ap, B, m0, n0, ka, k0, lda, ldb, t);
        } else {
            CP_COMMIT();   // keep group count in lockstep for CP_WAIT1
        }
    }

    // ---- epilogue ----
    float*  Cf = (float*)Cv  + (size_t)z * sC;
    __half* Ch = (__half*)Cv + (size_t)z * sC;
#pragma unroll
    for (int mi = 0; mi < 4; mi++) {
        const int r0 = m0 + mb + mi * 16 + gid;
#pragma unroll
        for (int nj = 0; nj < 4; nj++) {
            const int c0 = n0 + nb + nj * 8 + tig * 2;
            float v[4];
#pragma unroll
            for (int q = 0; q < 4; q++) v[q] = acc[mi][nj][q] * scale;
            if (ACT != ACT_NONE) {
                const float bb0 = __ldg(&bias[c0]);
                const float bb1 = __ldg(&bias[c0 + 1]);
                v[0] += bb0; v[1] += bb1; v[2] += bb0; v[3] += bb1;
            }
#pragma unroll
            for (int q = 0; q < 4; q++) {
                if (ACT == ACT_RELU) v[q] = fmaxf(v[q], 0.0f);
                if (ACT == ACT_GATE) {
                    const float sg = 1.0f / (1.0f + expf(-v[q]));
                    v[q] = sg * tanhf(v[q]);
                }
            }
            if (OUTF32) {
                *(float2*)&Cf[(size_t)r0 * ldc + c0]       = make_float2(v[0], v[1]);
                *(float2*)&Cf[(size_t)(r0 + 8) * ldc + c0] = make_float2(v[2], v[3]);
            } else {
                *(__half2*)&Ch[(size_t)r0 * ldc + c0] =
                    __floats2half2_rn(v[0], v[1]);
                *(__half2*)&Ch[(size_t)(r0 + 8) * ldc + c0] =
                    __floats2half2_rn(v[2], v[3]);
            }
        }
    }
}

// ---------------- fused prep ------------------------------------------------
// Segments: x->half; weight transposes; and a single-pass mem segment that
// reads each mem tile ONCE and emits memh (fp16 straight), out_tail (f32
// passthrough) and memt (fp16 transposed) — removes two full re-reads of mem.
__device__ __forceinline__ void do_transpose_h(
    const float* __restrict__ src, __half* __restrict__ dst,
    int R, int C, int tX, int tY, int t)
{
    __shared__ float tile[32][33];
    const int lx = t & 31, ly = t >> 5;   // 32 x 8
    const int x = tX * 32 + lx;
    const int y0 = tY * 32;
#pragma unroll
    for (int i = ly; i < 32; i += 8)
        tile[i][lx] = src[(size_t)(y0 + i) * C + x];
    __syncthreads();
    const int xo = tY * 32 + lx;
    const int yo0 = tX * 32;
#pragma unroll
    for (int i = ly; i < 32; i += 8)
        dst[(size_t)(yo0 + i) * R + xo] = __float2half_rn(tile[lx][i]);
}

// mem tile: read once -> memh + out_tail + memt(transposed)
__device__ __forceinline__ void do_mem_tile(
    const float* __restrict__ mem_z, __half* __restrict__ memh_z,
    float* __restrict__ tail_z, __half* __restrict__ memt_z,
    int tX, int tY, int t)
{
    __shared__ float tile[32][33];
    const int lx = t & 31, ly = t >> 5;   // 32 x 8
    const int x = tX * 32 + lx;           // col in [0,1024)
    const int y0 = tY * 32;               // row in [0,512)
#pragma unroll
    for (int i = ly; i < 32; i += 8) {
        const float v = mem_z[(size_t)(y0 + i) * DIN + x];
        tile[i][lx] = v;
        memh_z[(size_t)(y0 + i) * DIN + x] = __float2half_rn(v);
        tail_z[(size_t)(y0 + i) * DIN + x] = v;
    }
    __syncthreads();
    const int xo = tY * 32 + lx;          // col in memt [0,512)
    const int yo0 = tX * 32;              // row in memt [0,1024)
#pragma unroll
    for (int i = ly; i < 32; i += 8)
        memt_z[(size_t)(yo0 + i) * LMEM + xo] = __float2half_rn(tile[lx][i]);
}

static constexpr int PB_RX   = 16384;   // x -> half     (16M floats)
static constexpr int PB_W1   = 1024;    // W1t
static constexpr int PB_WM   = 1024;    // Wmt
static constexpr int PB_W2   = 2048;    // W2t
static constexpr int PB_MEM  = 4096;    // mem single-pass (z=8, 512 tiles each)
static constexpr int PREP_BLOCKS = PB_RX + PB_W1 + PB_WM + PB_W2 + PB_MEM;

__global__ void __launch_bounds__(256)
prep_k(const float* __restrict__ x, const float* __restrict__ mem,
       const float* __restrict__ W1, const float* __restrict__ Wm,
       const float* __restrict__ W2,
       __half* __restrict__ xh, __half* __restrict__ memh,
       __half* __restrict__ w1t, __half* __restrict__ wmt,
       __half* __restrict__ w2t, __half* __restrict__ memt,
       float* __restrict__ out_tail)
{
    int b = blockIdx.x;
    const int t = threadIdx.x;
    if (b < PB_RX) {
        const int i = b * 256 + t;
        float4 v = ((const float4*)x)[i];
        ((uint2*)xh)[i] = make_uint2(
            h2u(__floats2half2_rn(v.x, v.y)),
            h2u(__floats2half2_rn(v.z, v.w)));
        return;
    }
    b -= PB_RX;
    if (b < PB_W1) { do_transpose_h(W1, w1t, DIN, HID, b & 31, b >> 5, t); return; }
    b -= PB_W1;
    if (b < PB_WM) { do_transpose_h(Wm, wmt, DIN, HID, b & 31, b >> 5, t); return; }
    b -= PB_WM;
    if (b < PB_W2) { do_transpose_h(W2, w2t, 2 * DIN, HID, b & 31, b >> 5, t); return; }
    b -= PB_W2;
    {
        const int z = b >> 9;            // 512 tiles per batch (32 x 16)
        const int r = b & 511;
        const size_t off = (size_t)z * LMEM * DIN;
        do_mem_tile(mem + off, memh + off, out_tail + off, memt + off,
                    r & 31, r >> 5, t);
    }
}

// ---------------- masked softmax: f32 logits in, fp16 probs out -----------
__global__ void softmax_w(const float* __restrict__ att, __half* __restrict__ attp,
                          const float* __restrict__ mask)
{
    const int gw = blockIdx.x * 8 + (threadIdx.x >> 5);
    const int lane = threadIdx.x & 31;
    const float4* p4 = (const float4*)(att + (size_t)gw * LMEM);
    const float4* m4 = (const float4*)(mask + (size_t)(gw >> 11) * LMEM);

    float4 v[4];
    float mx = -3.4e38f;
#pragma unroll
    for (int q = 0; q < 4; q++) {
        float4 a = p4[lane + q * 32];
        float4 mm = m4[lane + q * 32];
        a.x -= 1e30f * (1.0f - mm.x);
        a.y -= 1e30f * (1.0f - mm.y);
        a.z -= 1e30f * (1.0f - mm.z);
        a.w -= 1e30f * (1.0f - mm.w);
        v[q] = a;
        mx = fmaxf(mx, fmaxf(fmaxf(a.x, a.y), fmaxf(a.z, a.w)));
    }
#pragma unroll
    for (int s = 16; s > 0; s >>= 1)
        mx = fmaxf(mx, __shfl_xor_sync(0xffffffffu, mx, s));
    float sum = 0.0f;
#pragma unroll
    for (int q = 0; q < 4; q++) {
        v[q].x = __expf(v[q].x - mx);
        v[q].y = __expf(v[q].y - mx);
        v[q].z = __expf(v[q].z - mx);
        v[q].w = __expf(v[q].w - mx);
        sum += v[q].x + v[q].y + v[q].z + v[q].w;
    }
#pragma unroll
    for (int s = 16; s > 0; s >>= 1)
        sum += __shfl_xor_sync(0xffffffffu, sum, s);
    const float inv = 1.0f / sum;
    uint2* o2 = (uint2*)(attp + (size_t)gw * LMEM);   // 8B = 4 halves
#pragma unroll
    for (int q = 0; q < 4; q++) {
        o2[lane + q * 32] = make_uint2(
            h2u(__floats2half2_rn(v[q].x * inv, v[q].y * inv)),
            h2u(__floats2half2_rn(v[q].z * inv, v[q].w * inv)));
    }
}

// ---------------- launch ---------------------------------------------------
extern "C" void kernel_launch(void* const* d_in, const int* in_sizes, int n_in,
                              void* d_out, int out_size)
{
    const float* x    = (const float*)d_in[0];
    const float* mem  = (const float*)d_in[1];
    const float* mask = (const float*)d_in[2];
    const float* W1   = (const float*)d_in[3];
    const float* b1   = (const float*)d_in[4];
    const float* Wm   = (const float*)d_in[5];
    const float* bm   = (const float*)d_in[6];
    const float* W2   = (const float*)d_in[7];
    const float* b2   = (const float*)d_in[8];
    float* out = (float*)d_out;

    __half *p_id, *p_md, *p_attp, *p_oo, *p_w1t, *p_wmt, *p_w2t, *p_memt, *p_xh, *p_memh;
    float *p_att;
    cudaGetSymbolAddress((void**)&p_id,   g_input_dot);
    cudaGetSymbolAddress((void**)&p_md,   g_memory_dot);
    cudaGetSymbolAddress((void**)&p_att,  g_att);
    cudaGetSymbolAddress((void**)&p_attp, g_attp);
    cudaGetSymbolAddress((void**)&p_oo,   g_out_one);
    cudaGetSymbolAddress((void**)&p_w1t,  g_w1t);
    cudaGetSymbolAddress((void**)&p_wmt,  g_wmt);
    cudaGetSymbolAddress((void**)&p_w2t,  g_w2t);
    cudaGetSymbolAddress((void**)&p_memt, g_memt);
    cudaGetSymbolAddress((void**)&p_xh,   g_xh);
    cudaGetSymbolAddress((void**)&p_memh, g_memh);

    cudaFuncSetAttribute(mma_gemm<ACT_RELU, false, false, true>,
                         cudaFuncAttributeMaxDynamicSharedMemorySize, GEMM_SMEM);
    cudaFuncSetAttribute(mma_gemm<ACT_NONE, false, true, false>,
                         cudaFuncAttributeMaxDynamicSharedMemorySize, GEMM_SMEM);
    cudaFuncSetAttribute(mma_gemm<ACT_NONE, false, false, false>,
                         cudaFuncAttributeMaxDynamicSharedMemorySize, GEMM_SMEM);
    cudaFuncSetAttribute(mma_gemm<ACT_GATE, true, true, false>,
                         cudaFuncAttributeMaxDynamicSharedMemorySize, GEMM_SMEM);

    // 0) fused operand conditioning + mem passthrough, ONE launch
    prep_k<<<PREP_BLOCKS, 256>>>(x, mem, W1, Wm, W2,
                                 p_xh, p_memh, p_w1t, p_wmt, p_w2t, p_memt,
                                 out + (size_t)NB * LDQ * HID);

    // 1+2) input_dot = relu(x@W1+b1) [16384,1024] AND
    //      memory_dot = relu(mem@Wm+bm) [4096,1024], fused: grid.y = 128+32
    mma_gemm<ACT_RELU, false, false, true>
        <<<dim3(HID / 128, (NB * LDQ) / 128 + (NB * LMEM) / 128, 1), 256, GEMM_SMEM>>>(
        p_xh, p_xh, p_w1t, b1, p_id, DIN, DIN, DIN, DIN, HID, 0, 0, 0, 1.0f,
        p_memh, p_wmt, bm, p_md, (NB * LDQ) / 128);

    // 3) att = input_dot @ memory_dot^T / 32      [8][2048,512] K=1024, F32 out
    mma_gemm<ACT_NONE, false, true, false><<<dim3(LMEM / 128, LDQ / 128, NB), 256, GEMM_SMEM>>>(
        p_id, p_id, p_md, nullptr, p_att, HID, HID, HID, HID, LMEM,
        (long long)LDQ * HID, (long long)LMEM * HID, (long long)LDQ * LMEM, 1.0f / 32.0f,
        nullptr, nullptr, nullptr, nullptr, 1 << 30);

    // 4) masked softmax: f32 logits -> fp16 probabilities
    softmax_w<<<(NB * LDQ) / 8, 256>>>(p_att, p_attp, mask);

    // 5) out_one = att @ mem                       [8][2048,1024] K=512, half out
    mma_gemm<ACT_NONE, false, false, false><<<dim3(DIN / 128, LDQ / 128, NB), 256, GEMM_SMEM>>>(
        p_attp, p_attp, p_memt, nullptr, p_oo, LMEM, LMEM, LMEM, LMEM, DIN,
        (long long)LDQ * LMEM, (long long)DIN * LMEM, (long long)LDQ * DIN, 1.0f,
        nullptr, nullptr, nullptr, nullptr, 1 << 30);

    // 6) out = gate(concat(x, out_one) @ W2 + b2)  [16384,1024] K=2048, F32 out
    mma_gemm<ACT_GATE, true, true, false><<<dim3(HID / 128, (NB * LDQ) / 128, 1), 256, GEMM_SMEM>>>(
        p_xh, p_oo, p_w2t, b2, out, 2 * DIN, DIN, DIN, 2 * DIN, HID, 0, 0, 0, 1.0f,
        nullptr, nullptr, nullptr, nullptr, 1 << 30);
}